// round 14
// baseline (speedup 1.0000x reference)
#include <cuda_runtime.h>
#include <cuda_bf16.h>
#include <cstdint>
#include <math.h>

// SupCon loss, N=8192, D=512, T=0.1
// bf16 mma.sync GEMM, upper-triangular tiles (S symmetric), dual fused
// epilogue. Grid balanced to exactly 7 waves (2072 CTAs, 8 CTAs take 2 diag tiles).

#define NPTS 8192
#define DDIM 512
#define NBLK 64
#define NOFFD (NBLK * (NBLK - 1) / 2)       // 2016
#define NGRID 2072                          // 296 * 7 exactly

// dynamic smem layout (bytes)
#define SM_A    0            // 2 stages x 16384
#define SM_B    32768        // 2 stages x 16384
#define SM_RLAB 65536        // 128 int
#define SM_CLAB 66048        // 128 int
#define SM_REDR 66560        // 512 float4 = 8192
#define SM_REDC 74752        // 256 float4 = 4096
#define SM_TOTAL 78848

__device__ __nv_bfloat16 g_ebf[NPTS * DDIM];     // 8 MB bf16 embeddings
__device__ float4 g_part[NBLK][NPTS];            // 8 MB partials
__device__ int g_hist[16];

__device__ __forceinline__ uint32_t smem_u32(const void* p) {
    uint32_t a;
    asm("{ .reg .u64 t; cvta.to.shared.u64 t, %1; cvt.u32.u64 %0, t; }" : "=r"(a) : "l"(p));
    return a;
}
__device__ __forceinline__ float ex2f(float x) {
    float y; asm("ex2.approx.f32 %0, %1;" : "=f"(y) : "f"(x)); return y;
}
__device__ __forceinline__ void cpasync16(uint32_t saddr, const void* g) {
    asm volatile("cp.async.cg.shared.global [%0], [%1], 16;" :: "r"(saddr), "l"(g));
}
__device__ __forceinline__ void ldsm4(uint32_t* r, uint32_t addr) {
    asm volatile("ldmatrix.sync.aligned.m8n8.x4.shared.b16 {%0,%1,%2,%3}, [%4];"
                 : "=r"(r[0]), "=r"(r[1]), "=r"(r[2]), "=r"(r[3]) : "r"(addr));
}
__device__ __forceinline__ void mma_bf16(float* c, const uint32_t* a, uint32_t b0, uint32_t b1) {
    asm volatile("mma.sync.aligned.m16n8k16.row.col.f32.bf16.bf16.f32 "
                 "{%0,%1,%2,%3}, {%4,%5,%6,%7}, {%8,%9}, {%0,%1,%2,%3};"
                 : "+f"(c[0]), "+f"(c[1]), "+f"(c[2]), "+f"(c[3])
                 : "r"(a[0]), "r"(a[1]), "r"(a[2]), "r"(a[3]), "r"(b0), "r"(b1));
}

// ---------------- fp32 -> bf16 ----------------
__global__ void __launch_bounds__(256)
conv_kernel(const float* __restrict__ emb)
{
    int i = (blockIdx.x * 256 + threadIdx.x) * 8;
    float4 v0 = *reinterpret_cast<const float4*>(emb + i);
    float4 v1 = *reinterpret_cast<const float4*>(emb + i + 4);
    __nv_bfloat162 b0 = __float22bfloat162_rn(make_float2(v0.x, v0.y));
    __nv_bfloat162 b1 = __float22bfloat162_rn(make_float2(v0.z, v0.w));
    __nv_bfloat162 b2 = __float22bfloat162_rn(make_float2(v1.x, v1.y));
    __nv_bfloat162 b3 = __float22bfloat162_rn(make_float2(v1.z, v1.w));
    uint4 o;
    o.x = *reinterpret_cast<uint32_t*>(&b0);
    o.y = *reinterpret_cast<uint32_t*>(&b1);
    o.z = *reinterpret_cast<uint32_t*>(&b2);
    o.w = *reinterpret_cast<uint32_t*>(&b3);
    *reinterpret_cast<uint4*>(g_ebf + i) = o;
}

__global__ void supcon_zero(float* out) {
    if (threadIdx.x == 0) *out = 0.0f;
    if (threadIdx.x < 16) g_hist[threadIdx.x] = 0;
}

__global__ void __launch_bounds__(256)
hist_kernel(const long long* __restrict__ labels)
{
    __shared__ int h[16];
    if (threadIdx.x < 16) h[threadIdx.x] = 0;
    __syncthreads();
    atomicAdd(&h[(int)labels[blockIdx.x * 256 + threadIdx.x]], 1);
    __syncthreads();
    if (threadIdx.x < 16) atomicAdd(&g_hist[threadIdx.x], h[threadIdx.x]);
}

// ---------------- GEMM (upper-tri tiles) + dual fused epilogue ----------------
__global__ void __launch_bounds__(256, 2)
supcon_gemm(const long long* __restrict__ labels)
{
    extern __shared__ __align__(128) char smem[];
    int* rlab_s = (int*)(smem + SM_RLAB);
    int* clab_s = (int*)(smem + SM_CLAB);
    float4* red_r = (float4*)(smem + SM_REDR);
    float4* red_c = (float4*)(smem + SM_REDC);

    const int tid = threadIdx.x;
    const int wid = tid >> 5, lane = tid & 31;
    const int warp_m = wid >> 2, warp_n = wid & 3;
    const int bid = blockIdx.x;

    const uint32_t aBase = smem_u32(smem + SM_A);
    const uint32_t bBase = smem_u32(smem + SM_B);

    // ---- tile-independent addressing (hoisted out of the tile loop) ----
    const int ldr = tid >> 1;
    const int ldh = tid & 1;
    const int swl = ldr & 7;
    uint32_t stA[4], stB[4];
#pragma unroll
    for (int j = 0; j < 4; ++j) {
        const uint32_t off = (uint32_t)(ldr * 128 + (((ldh * 4 + j) ^ swl) * 16));
        stA[j] = aBase + off;
        stB[j] = bBase + off;
    }
    const int lrowA = warp_m * 64 + ((lane >> 3) & 1) * 8 + (lane & 7);
    const int lrowB = warp_n * 32 + ((lane >> 3) & 1) * 8 + (lane & 7);
    const int hi    = lane >> 4;
    const uint32_t rowA = aBase + (uint32_t)(lrowA * 128);
    const uint32_t rowB = bBase + (uint32_t)(lrowB * 128);
    uint32_t colA[4], colB[4];
#pragma unroll
    for (int s = 0; s < 4; ++s) {
        colA[s] = (uint32_t)((((2 * s + hi) ^ (lrowA & 7))) * 16);
        colB[s] = (uint32_t)((((2 * s + hi) ^ (lrowB & 7))) * 16);
    }

    const float Cc = 14.4269504088896341f;   // 1/(T*ln2), T=0.1
    const int g  = lane >> 2;
    const int qq = lane & 3;

    const int ntiles = (bid < 8) ? 2 : 1;

    for (int it = 0; it < ntiles; ++it) {
        // ---- bid -> (I,J): 0-7 double diag, 8-55 single diag, rest off-diag ----
        int I, J;
        if (bid < 8) {
            I = J = bid * 2 + it;
        } else if (bid < 56) {
            I = J = 16 + (bid - 8);
        } else {
            int q = bid - 56; I = 0;
            while (q >= NBLK - 1 - I) { q -= NBLK - 1 - I; ++I; }
            J = I + 1 + q;
        }
        const int row0 = I * 128, col0 = J * 128;
        const bool offdiag = (I != J);

        if (tid < 128) rlab_s[tid] = (int)labels[row0 + tid];
        else           clab_s[tid - 128] = (int)labels[col0 + tid - 128];

        const __nv_bfloat16* gA = g_ebf + (size_t)(row0 + ldr) * DDIM + ldh * 32;
        const __nv_bfloat16* gB = g_ebf + (size_t)(col0 + ldr) * DDIM + ldh * 32;

        float ca[4][4][4];
#pragma unroll
        for (int a = 0; a < 4; a++)
#pragma unroll
            for (int b = 0; b < 4; b++)
#pragma unroll
                for (int c = 0; c < 4; c++) ca[a][b][c] = 0.0f;

        // prologue: stage 0
#pragma unroll
        for (int j = 0; j < 4; ++j) {
            cpasync16(stA[j], gA + j * 8);
            cpasync16(stB[j], gB + j * 8);
        }
        asm volatile("cp.async.commit_group;");

        for (int kt = 0; kt < 8; ++kt) {
            if (kt + 1 < 8) {
                const uint32_t off = (uint32_t)(((kt + 1) & 1) * 16384);
                const __nv_bfloat16* ga = gA + (kt + 1) * 64;
                const __nv_bfloat16* gb = gB + (kt + 1) * 64;
#pragma unroll
                for (int j = 0; j < 4; ++j) {
                    cpasync16(stA[j] + off, ga + j * 8);
                    cpasync16(stB[j] + off, gb + j * 8);
                }
                asm volatile("cp.async.commit_group;");
                asm volatile("cp.async.wait_group 1;");
            } else {
                asm volatile("cp.async.wait_group 0;");
            }
            __syncthreads();

            const uint32_t boff = (uint32_t)((kt & 1) * 16384);
#pragma unroll
            for (int s = 0; s < 4; ++s) {
                uint32_t af[4][4], bfr[2][4];
#pragma unroll
                for (int mf = 0; mf < 4; ++mf)
                    ldsm4(af[mf], rowA + boff + colA[s] + (uint32_t)(mf * 2048));
#pragma unroll
                for (int ng = 0; ng < 2; ++ng)
                    ldsm4(bfr[ng], rowB + boff + colB[s] + (uint32_t)(ng * 2048));
#pragma unroll
                for (int mf = 0; mf < 4; ++mf)
#pragma unroll
                    for (int nf = 0; nf < 4; ++nf) {
                        int ng = nf >> 1, u = nf & 1;
                        mma_bf16(ca[mf][nf], af[mf], bfr[ng][u], bfr[ng][2 + u]);
                    }
            }
            __syncthreads();
        }

        // hoist labels into registers: 8 rows, 8 cols per thread
        int rl[8], cl[8];
#pragma unroll
        for (int mf = 0; mf < 4; ++mf)
#pragma unroll
            for (int h = 0; h < 2; ++h)
                rl[mf * 2 + h] = rlab_s[warp_m * 64 + mf * 16 + h * 8 + g];
#pragma unroll
        for (int nf = 0; nf < 4; ++nf)
#pragma unroll
            for (int e = 0; e < 2; ++e)
                cl[nf * 2 + e] = clab_s[warp_n * 32 + nf * 8 + qq * 2 + e];

        if (offdiag) {
            // ---- row-side: per-row max, no diag checks ----
#pragma unroll
            for (int mf = 0; mf < 4; ++mf) {
#pragma unroll
                for (int h = 0; h < 2; ++h) {
                    const int lrow = warp_m * 64 + mf * 16 + h * 8 + g;
                    const int rlv = rl[mf * 2 + h];
                    float tm = -1e30f, ps = 0.0f;
#pragma unroll
                    for (int nf = 0; nf < 4; ++nf)
#pragma unroll
                        for (int e = 0; e < 2; ++e) {
                            const float d = ca[mf][nf][h * 2 + e];
                            tm = fmaxf(tm, d);
                            if (cl[nf * 2 + e] == rlv) ps += d;
                        }
                    tm = fmaxf(tm, __shfl_xor_sync(0xFFFFFFFFu, tm, 1));
                    tm = fmaxf(tm, __shfl_xor_sync(0xFFFFFFFFu, tm, 2));
                    const float tms = tm * Cc;
                    float l = 0.0f;
#pragma unroll
                    for (int nf = 0; nf < 4; ++nf)
#pragma unroll
                        for (int e = 0; e < 2; ++e)
                            l += ex2f(fmaf(ca[mf][nf][h * 2 + e], Cc, -tms));
                    l  += __shfl_xor_sync(0xFFFFFFFFu, l, 1);
                    l  += __shfl_xor_sync(0xFFFFFFFFu, l, 2);
                    ps += __shfl_xor_sync(0xFFFFFFFFu, ps, 1);
                    ps += __shfl_xor_sync(0xFFFFFFFFu, ps, 2);
                    if (qq == 0) red_r[lrow * 4 + warp_n] = make_float4(tms, l, ps, 0.0f);
                }
            }
            // ---- col-side: per-col max, no diag checks ----
#pragma unroll
            for (int nf = 0; nf < 4; ++nf) {
#pragma unroll
                for (int e = 0; e < 2; ++e) {
                    const int lcol = warp_n * 32 + nf * 8 + qq * 2 + e;
                    const int clv = cl[nf * 2 + e];
                    float tm = -1e30f, ps = 0.0f;
#pragma unroll
                    for (int mf = 0; mf < 4; ++mf)
#pragma unroll
                        for (int h = 0; h < 2; ++h) {
                            const float d = ca[mf][nf][h * 2 + e];
                            tm = fmaxf(tm, d);
                            if (rl[mf * 2 + h] == clv) ps += d;
                        }
                    tm = fmaxf(tm, __shfl_xor_sync(0xFFFFFFFFu, tm, 4));
                    tm = fmaxf(tm, __shfl_xor_sync(0xFFFFFFFFu, tm, 8));
                    tm = fmaxf(tm, __shfl_xor_sync(0xFFFFFFFFu, tm, 16));
                    const float tms = tm * Cc;
                    float l = 0.0f;
#pragma unroll
                    for (int mf = 0; mf < 4; ++mf)
#pragma unroll
                        for (int h = 0; h < 2; ++h)
                            l += ex2f(fmaf(ca[mf][nf][h * 2 + e], Cc, -tms));
                    l  += __shfl_xor_sync(0xFFFFFFFFu, l, 4);
                    l  += __shfl_xor_sync(0xFFFFFFFFu, l, 8);
                    l  += __shfl_xor_sync(0xFFFFFFFFu, l, 16);
                    ps += __shfl_xor_sync(0xFFFFFFFFu, ps, 4);
                    ps += __shfl_xor_sync(0xFFFFFFFFu, ps, 8);
                    ps += __shfl_xor_sync(0xFFFFFFFFu, ps, 16);
                    if (g == 0) red_c[lcol * 2 + warp_m] = make_float4(tms, l, ps, 0.0f);
                }
            }
        } else {
            // ---- diagonal tile: exact path with per-element diag exclusion ----
#pragma unroll
            for (int mf = 0; mf < 4; ++mf) {
#pragma unroll
                for (int h = 0; h < 2; ++h) {
                    const int lrow = warp_m * 64 + mf * 16 + h * 8 + g;
                    const int grow = row0 + lrow;
                    const int rlv = rl[mf * 2 + h];
                    float tm = -1e30f, ps = 0.0f;
#pragma unroll
                    for (int nf = 0; nf < 4; ++nf)
#pragma unroll
                        for (int e = 0; e < 2; ++e) {
                            const int lcol = warp_n * 32 + nf * 8 + qq * 2 + e;
                            const float d = ca[mf][nf][h * 2 + e];
                            const bool diag = (grow == col0 + lcol);
                            if (!diag) tm = fmaxf(tm, d);
                            if (!diag && cl[nf * 2 + e] == rlv) ps += d;
                        }
                    tm = fmaxf(tm, __shfl_xor_sync(0xFFFFFFFFu, tm, 1));
                    tm = fmaxf(tm, __shfl_xor_sync(0xFFFFFFFFu, tm, 2));
                    const float tms = tm * Cc;
                    float l = 0.0f;
#pragma unroll
                    for (int nf = 0; nf < 4; ++nf)
#pragma unroll
                        for (int e = 0; e < 2; ++e) {
                            const int lcol = warp_n * 32 + nf * 8 + qq * 2 + e;
                            const bool diag = (grow == col0 + lcol);
                            if (!diag) l += ex2f(fmaf(ca[mf][nf][h * 2 + e], Cc, -tms));
                        }
                    l  += __shfl_xor_sync(0xFFFFFFFFu, l, 1);
                    l  += __shfl_xor_sync(0xFFFFFFFFu, l, 2);
                    ps += __shfl_xor_sync(0xFFFFFFFFu, ps, 1);
                    ps += __shfl_xor_sync(0xFFFFFFFFu, ps, 2);
                    if (qq == 0) red_r[lrow * 4 + warp_n] = make_float4(tms, l, ps, 0.0f);
                }
            }
        }

        __syncthreads();

        // ---- intra-CTA merges + partial writes ----
        if (tid < 128) {
            float4 p0 = red_r[tid * 4 + 0];
            float4 p1 = red_r[tid * 4 + 1];
            float4 p2 = red_r[tid * 4 + 2];
            float4 p3 = red_r[tid * 4 + 3];
            float m = fmaxf(fmaxf(p0.x, p1.x), fmaxf(p2.x, p3.x));
            float l = p0.y * ex2f(p0.x - m) + p1.y * ex2f(p1.x - m)
                    + p2.y * ex2f(p2.x - m) + p3.y * ex2f(p3.x - m);
            g_part[J][row0 + tid] = make_float4(m, l, p0.z + p1.z + p2.z + p3.z, 0.0f);
        } else if (offdiag) {
            const int c = tid - 128;
            float4 p = red_c[c * 2 + 0];
            float4 q = red_c[c * 2 + 1];
            float mn = fmaxf(p.x, q.x);
            float l = p.y * ex2f(p.x - mn) + q.y * ex2f(q.x - mn);
            g_part[I][col0 + c] = make_float4(mn, l, p.z + q.z, 0.0f);
        }

        __syncthreads();   // protect labels/red arrays/smem tiles for next tile
    }
}

// ---------------- final per-row merge + loss reduction ----------------
__global__ void __launch_bounds__(256)
supcon_reduce(const long long* __restrict__ labels, float* __restrict__ out)
{
    const int wid = threadIdx.x >> 5, lane = threadIdx.x & 31;
    const int row = blockIdx.x * 8 + wid;

    float4 a = g_part[lane][row];
    float4 b = g_part[lane + 32][row];
    float m = fmaxf(a.x, b.x);
    float l = a.y * ex2f(a.x - m) + b.y * ex2f(b.x - m);
    float ps = a.z + b.z;
#pragma unroll
    for (int off = 16; off > 0; off >>= 1) {
        float mo = __shfl_down_sync(0xFFFFFFFFu, m, off);
        float lo = __shfl_down_sync(0xFFFFFFFFu, l, off);
        float po = __shfl_down_sync(0xFFFFFFFFu, ps, off);
        float mn = fmaxf(m, mo);
        l = l * ex2f(m - mn) + lo * ex2f(mo - mn);
        m = mn; ps += po;
    }

    __shared__ float sred[8];
    const float LN2 = 0.6931471805599453f;
    const float T = 0.1f;
    if (lane == 0) {
        float cn = (float)(g_hist[(int)labels[row]] - 1);
        sred[wid] = (m + log2f(l)) * (LN2 * T / (float)NPTS) - ps / (cn * (float)NPTS);
    }
    __syncthreads();
    if (threadIdx.x < 8) {
        float v = sred[threadIdx.x];
#pragma unroll
        for (int off = 4; off > 0; off >>= 1)
            v += __shfl_down_sync(0xFFu, v, off);
        if (threadIdx.x == 0) atomicAdd(out, v);
    }
}

extern "C" void kernel_launch(void* const* d_in, const int* in_sizes, int n_in,
                              void* d_out, int out_size)
{
    const float*     emb    = (const float*)d_in[0];
    const long long* labels = (const long long*)d_in[1];
    float*           out    = (float*)d_out;

    cudaFuncSetAttribute(supcon_gemm, cudaFuncAttributeMaxDynamicSharedMemorySize, SM_TOTAL);

    supcon_zero<<<1, 32>>>(out);
    hist_kernel<<<NPTS / 256, 256>>>(labels);
    conv_kernel<<<NPTS * DDIM / 8 / 256, 256>>>(emb);
    supcon_gemm<<<NGRID, 256, SM_TOTAL>>>(labels);
    supcon_reduce<<<NPTS / 8, 256>>>(labels, out);
}

// round 16
// speedup vs baseline: 1.0537x; 1.0537x over previous
#include <cuda_runtime.h>
#include <cuda_bf16.h>
#include <cstdint>
#include <math.h>

// SupCon loss, N=8192, D=512, T=0.1
// bf16 mma.sync GEMM, upper-triangular tiles (S symmetric), dual fused
// epilogue (round-13 proven). Single-barrier cp.async mainloop.

#define NPTS 8192
#define DDIM 512
#define NBLK 64
#define NTILES_UT (NBLK * (NBLK + 1) / 2)   // 2080
#define NOFFD (NBLK * (NBLK - 1) / 2)       // 2016

// dynamic smem layout (bytes)
#define SM_A    0            // 2 stages x 16384
#define SM_B    32768        // 2 stages x 16384
#define SM_RLAB 65536        // 128 int
#define SM_CLAB 66048        // 128 int
#define SM_REDR 66560        // 512 float4 = 8192
#define SM_REDC 74752        // 256 float4 = 4096
#define SM_TOTAL 78848

__device__ __nv_bfloat16 g_ebf[NPTS * DDIM];     // 8 MB bf16 embeddings
__device__ float4 g_part[NBLK][NPTS];            // 8 MB partials
__device__ int g_hist[16];

__device__ __forceinline__ uint32_t smem_u32(const void* p) {
    uint32_t a;
    asm("{ .reg .u64 t; cvta.to.shared.u64 t, %1; cvt.u32.u64 %0, t; }" : "=r"(a) : "l"(p));
    return a;
}
__device__ __forceinline__ float ex2f(float x) {
    float y; asm("ex2.approx.f32 %0, %1;" : "=f"(y) : "f"(x)); return y;
}
__device__ __forceinline__ void cpasync16(uint32_t saddr, const void* g) {
    asm volatile("cp.async.cg.shared.global [%0], [%1], 16;" :: "r"(saddr), "l"(g));
}
__device__ __forceinline__ void ldsm4(uint32_t* r, uint32_t addr) {
    asm volatile("ldmatrix.sync.aligned.m8n8.x4.shared.b16 {%0,%1,%2,%3}, [%4];"
                 : "=r"(r[0]), "=r"(r[1]), "=r"(r[2]), "=r"(r[3]) : "r"(addr));
}
__device__ __forceinline__ void mma_bf16(float* c, const uint32_t* a, uint32_t b0, uint32_t b1) {
    asm volatile("mma.sync.aligned.m16n8k16.row.col.f32.bf16.bf16.f32 "
                 "{%0,%1,%2,%3}, {%4,%5,%6,%7}, {%8,%9}, {%0,%1,%2,%3};"
                 : "+f"(c[0]), "+f"(c[1]), "+f"(c[2]), "+f"(c[3])
                 : "r"(a[0]), "r"(a[1]), "r"(a[2]), "r"(a[3]), "r"(b0), "r"(b1));
}

// ---------------- fp32 -> bf16 ----------------
__global__ void __launch_bounds__(256)
conv_kernel(const float* __restrict__ emb)
{
    int i = (blockIdx.x * 256 + threadIdx.x) * 8;
    float4 v0 = *reinterpret_cast<const float4*>(emb + i);
    float4 v1 = *reinterpret_cast<const float4*>(emb + i + 4);
    __nv_bfloat162 b0 = __float22bfloat162_rn(make_float2(v0.x, v0.y));
    __nv_bfloat162 b1 = __float22bfloat162_rn(make_float2(v0.z, v0.w));
    __nv_bfloat162 b2 = __float22bfloat162_rn(make_float2(v1.x, v1.y));
    __nv_bfloat162 b3 = __float22bfloat162_rn(make_float2(v1.z, v1.w));
    uint4 o;
    o.x = *reinterpret_cast<uint32_t*>(&b0);
    o.y = *reinterpret_cast<uint32_t*>(&b1);
    o.z = *reinterpret_cast<uint32_t*>(&b2);
    o.w = *reinterpret_cast<uint32_t*>(&b3);
    *reinterpret_cast<uint4*>(g_ebf + i) = o;
}

__global__ void supcon_zero(float* out) {
    if (threadIdx.x == 0) *out = 0.0f;
    if (threadIdx.x < 16) g_hist[threadIdx.x] = 0;
}

__global__ void __launch_bounds__(256)
hist_kernel(const long long* __restrict__ labels)
{
    __shared__ int h[16];
    if (threadIdx.x < 16) h[threadIdx.x] = 0;
    __syncthreads();
    atomicAdd(&h[(int)labels[blockIdx.x * 256 + threadIdx.x]], 1);
    __syncthreads();
    if (threadIdx.x < 16) atomicAdd(&g_hist[threadIdx.x], h[threadIdx.x]);
}

// ---------------- GEMM (upper-tri tiles) + dual fused epilogue ----------------
__global__ void __launch_bounds__(256, 2)
supcon_gemm(const long long* __restrict__ labels)
{
    extern __shared__ __align__(128) char smem[];
    int* rlab_s = (int*)(smem + SM_RLAB);
    int* clab_s = (int*)(smem + SM_CLAB);
    float4* red_r = (float4*)(smem + SM_REDR);
    float4* red_c = (float4*)(smem + SM_REDC);

    const int tid = threadIdx.x;
    const int wid = tid >> 5, lane = tid & 31;
    const int warp_m = wid >> 2, warp_n = wid & 3;

    // bid -> (I,J): off-diagonal tiles first, diagonal tiles last (cheap tail)
    int I, J;
    if (blockIdx.x < NOFFD) {
        int q = blockIdx.x; I = 0;
        while (q >= NBLK - 1 - I) { q -= NBLK - 1 - I; ++I; }
        J = I + 1 + q;
    } else {
        I = J = blockIdx.x - NOFFD;
    }
    const int row0 = I * 128, col0 = J * 128;
    const bool offdiag = (I != J);

    if (tid < 128) rlab_s[tid] = (int)labels[row0 + tid];
    else           clab_s[tid - 128] = (int)labels[col0 + tid - 128];

    const uint32_t aBase = smem_u32(smem + SM_A);
    const uint32_t bBase = smem_u32(smem + SM_B);

    // ---- cp.async mapping: row = tid>>1, half = tid&1 ----
    const int ldr = tid >> 1;
    const int ldh = tid & 1;
    const int swl = ldr & 7;
    uint32_t stA[4], stB[4];
#pragma unroll
    for (int j = 0; j < 4; ++j) {
        const uint32_t off = (uint32_t)(ldr * 128 + (((ldh * 4 + j) ^ swl) * 16));
        stA[j] = aBase + off;
        stB[j] = bBase + off;
    }
    const __nv_bfloat16* gA = g_ebf + (size_t)(row0 + ldr) * DDIM + ldh * 32;
    const __nv_bfloat16* gB = g_ebf + (size_t)(col0 + ldr) * DDIM + ldh * 32;

    // ---- ldmatrix addressing ----
    const int lrowA = warp_m * 64 + ((lane >> 3) & 1) * 8 + (lane & 7);
    const int lrowB = warp_n * 32 + ((lane >> 3) & 1) * 8 + (lane & 7);
    const int hi    = lane >> 4;
    const uint32_t rowA = aBase + (uint32_t)(lrowA * 128);
    const uint32_t rowB = bBase + (uint32_t)(lrowB * 128);
    uint32_t colA[4], colB[4];
#pragma unroll
    for (int s = 0; s < 4; ++s) {
        colA[s] = (uint32_t)((((2 * s + hi) ^ (lrowA & 7))) * 16);
        colB[s] = (uint32_t)((((2 * s + hi) ^ (lrowB & 7))) * 16);
    }

    float ca[4][4][4];
#pragma unroll
    for (int a = 0; a < 4; a++)
#pragma unroll
        for (int b = 0; b < 4; b++)
#pragma unroll
            for (int c = 0; c < 4; c++) ca[a][b][c] = 0.0f;

    // prologue: stage 0
#pragma unroll
    for (int j = 0; j < 4; ++j) {
        cpasync16(stA[j], gA + j * 8);
        cpasync16(stB[j], gB + j * 8);
    }
    asm volatile("cp.async.commit_group;");

    for (int kt = 0; kt < 8; ++kt) {
        // stage kt is the only pending group; wait for it, then one barrier.
        asm volatile("cp.async.wait_group 0;");
        __syncthreads();
        // All warps are past compute(kt-1), so buffer (kt+1)&1 is free to refill.
        if (kt + 1 < 8) {
            const uint32_t off = (uint32_t)(((kt + 1) & 1) * 16384);
            const __nv_bfloat16* ga = gA + (kt + 1) * 64;
            const __nv_bfloat16* gb = gB + (kt + 1) * 64;
#pragma unroll
            for (int j = 0; j < 4; ++j) {
                cpasync16(stA[j] + off, ga + j * 8);
                cpasync16(stB[j] + off, gb + j * 8);
            }
            asm volatile("cp.async.commit_group;");
        }

        const uint32_t boff = (uint32_t)((kt & 1) * 16384);
#pragma unroll
        for (int s = 0; s < 4; ++s) {
            uint32_t af[4][4], bfr[2][4];
#pragma unroll
            for (int mf = 0; mf < 4; ++mf)
                ldsm4(af[mf], rowA + boff + colA[s] + (uint32_t)(mf * 2048));
#pragma unroll
            for (int ng = 0; ng < 2; ++ng)
                ldsm4(bfr[ng], rowB + boff + colB[s] + (uint32_t)(ng * 2048));
#pragma unroll
            for (int mf = 0; mf < 4; ++mf)
#pragma unroll
                for (int nf = 0; nf < 4; ++nf) {
                    int ng = nf >> 1, u = nf & 1;
                    mma_bf16(ca[mf][nf], af[mf], bfr[ng][u], bfr[ng][2 + u]);
                }
        }
    }

    const float Cc = 14.4269504088896341f;   // 1/(T*ln2), T=0.1
    const int g  = lane >> 2;
    const int qq = lane & 3;

    // hoist labels into registers: 8 rows, 8 cols per thread
    int rl[8], cl[8];
#pragma unroll
    for (int mf = 0; mf < 4; ++mf)
#pragma unroll
        for (int h = 0; h < 2; ++h)
            rl[mf * 2 + h] = rlab_s[warp_m * 64 + mf * 16 + h * 8 + g];
#pragma unroll
    for (int nf = 0; nf < 4; ++nf)
#pragma unroll
        for (int e = 0; e < 2; ++e)
            cl[nf * 2 + e] = clab_s[warp_n * 32 + nf * 8 + qq * 2 + e];

    if (offdiag) {
        // ---- row-side: per-row max, no diag checks ----
#pragma unroll
        for (int mf = 0; mf < 4; ++mf) {
#pragma unroll
            for (int h = 0; h < 2; ++h) {
                const int lrow = warp_m * 64 + mf * 16 + h * 8 + g;
                const int rlv = rl[mf * 2 + h];
                float tm = -1e30f, ps = 0.0f;
#pragma unroll
                for (int nf = 0; nf < 4; ++nf)
#pragma unroll
                    for (int e = 0; e < 2; ++e) {
                        const float d = ca[mf][nf][h * 2 + e];
                        tm = fmaxf(tm, d);
                        if (cl[nf * 2 + e] == rlv) ps += d;
                    }
                tm = fmaxf(tm, __shfl_xor_sync(0xFFFFFFFFu, tm, 1));
                tm = fmaxf(tm, __shfl_xor_sync(0xFFFFFFFFu, tm, 2));
                const float tms = tm * Cc;
                float l = 0.0f;
#pragma unroll
                for (int nf = 0; nf < 4; ++nf)
#pragma unroll
                    for (int e = 0; e < 2; ++e)
                        l += ex2f(fmaf(ca[mf][nf][h * 2 + e], Cc, -tms));
                l  += __shfl_xor_sync(0xFFFFFFFFu, l, 1);
                l  += __shfl_xor_sync(0xFFFFFFFFu, l, 2);
                ps += __shfl_xor_sync(0xFFFFFFFFu, ps, 1);
                ps += __shfl_xor_sync(0xFFFFFFFFu, ps, 2);
                if (qq == 0) red_r[lrow * 4 + warp_n] = make_float4(tms, l, ps, 0.0f);
            }
        }
        // ---- col-side: per-col max, no diag checks ----
#pragma unroll
        for (int nf = 0; nf < 4; ++nf) {
#pragma unroll
            for (int e = 0; e < 2; ++e) {
                const int lcol = warp_n * 32 + nf * 8 + qq * 2 + e;
                const int clv = cl[nf * 2 + e];
                float tm = -1e30f, ps = 0.0f;
#pragma unroll
                for (int mf = 0; mf < 4; ++mf)
#pragma unroll
                    for (int h = 0; h < 2; ++h) {
                        const float d = ca[mf][nf][h * 2 + e];
                        tm = fmaxf(tm, d);
                        if (rl[mf * 2 + h] == clv) ps += d;
                    }
                tm = fmaxf(tm, __shfl_xor_sync(0xFFFFFFFFu, tm, 4));
                tm = fmaxf(tm, __shfl_xor_sync(0xFFFFFFFFu, tm, 8));
                tm = fmaxf(tm, __shfl_xor_sync(0xFFFFFFFFu, tm, 16));
                const float tms = tm * Cc;
                float l = 0.0f;
#pragma unroll
                for (int mf = 0; mf < 4; ++mf)
#pragma unroll
                    for (int h = 0; h < 2; ++h)
                        l += ex2f(fmaf(ca[mf][nf][h * 2 + e], Cc, -tms));
                l  += __shfl_xor_sync(0xFFFFFFFFu, l, 4);
                l  += __shfl_xor_sync(0xFFFFFFFFu, l, 8);
                l  += __shfl_xor_sync(0xFFFFFFFFu, l, 16);
                ps += __shfl_xor_sync(0xFFFFFFFFu, ps, 4);
                ps += __shfl_xor_sync(0xFFFFFFFFu, ps, 8);
                ps += __shfl_xor_sync(0xFFFFFFFFu, ps, 16);
                if (g == 0) red_c[lcol * 2 + warp_m] = make_float4(tms, l, ps, 0.0f);
            }
        }
    } else {
        // ---- diagonal tile: exact path with per-element diag exclusion ----
#pragma unroll
        for (int mf = 0; mf < 4; ++mf) {
#pragma unroll
            for (int h = 0; h < 2; ++h) {
                const int lrow = warp_m * 64 + mf * 16 + h * 8 + g;
                const int grow = row0 + lrow;
                const int rlv = rl[mf * 2 + h];
                float tm = -1e30f, ps = 0.0f;
#pragma unroll
                for (int nf = 0; nf < 4; ++nf)
#pragma unroll
                    for (int e = 0; e < 2; ++e) {
                        const int lcol = warp_n * 32 + nf * 8 + qq * 2 + e;
                        const float d = ca[mf][nf][h * 2 + e];
                        const bool diag = (grow == col0 + lcol);
                        if (!diag) tm = fmaxf(tm, d);
                        if (!diag && cl[nf * 2 + e] == rlv) ps += d;
                    }
                tm = fmaxf(tm, __shfl_xor_sync(0xFFFFFFFFu, tm, 1));
                tm = fmaxf(tm, __shfl_xor_sync(0xFFFFFFFFu, tm, 2));
                const float tms = tm * Cc;
                float l = 0.0f;
#pragma unroll
                for (int nf = 0; nf < 4; ++nf)
#pragma unroll
                    for (int e = 0; e < 2; ++e) {
                        const int lcol = warp_n * 32 + nf * 8 + qq * 2 + e;
                        const bool diag = (grow == col0 + lcol);
                        if (!diag) l += ex2f(fmaf(ca[mf][nf][h * 2 + e], Cc, -tms));
                    }
                l  += __shfl_xor_sync(0xFFFFFFFFu, l, 1);
                l  += __shfl_xor_sync(0xFFFFFFFFu, l, 2);
                ps += __shfl_xor_sync(0xFFFFFFFFu, ps, 1);
                ps += __shfl_xor_sync(0xFFFFFFFFu, ps, 2);
                if (qq == 0) red_r[lrow * 4 + warp_n] = make_float4(tms, l, ps, 0.0f);
            }
        }
    }

    __syncthreads();

    // ---- intra-CTA merges + partial writes ----
    if (tid < 128) {
        float4 p0 = red_r[tid * 4 + 0];
        float4 p1 = red_r[tid * 4 + 1];
        float4 p2 = red_r[tid * 4 + 2];
        float4 p3 = red_r[tid * 4 + 3];
        float m = fmaxf(fmaxf(p0.x, p1.x), fmaxf(p2.x, p3.x));
        float l = p0.y * ex2f(p0.x - m) + p1.y * ex2f(p1.x - m)
                + p2.y * ex2f(p2.x - m) + p3.y * ex2f(p3.x - m);
        g_part[J][row0 + tid] = make_float4(m, l, p0.z + p1.z + p2.z + p3.z, 0.0f);
    } else if (offdiag) {
        const int c = tid - 128;
        float4 p = red_c[c * 2 + 0];
        float4 q = red_c[c * 2 + 1];
        float mn = fmaxf(p.x, q.x);
        float l = p.y * ex2f(p.x - mn) + q.y * ex2f(q.x - mn);
        g_part[I][col0 + c] = make_float4(mn, l, p.z + q.z, 0.0f);
    }
}

// ---------------- final per-row merge + loss reduction ----------------
__global__ void __launch_bounds__(256)
supcon_reduce(const long long* __restrict__ labels, float* __restrict__ out)
{
    const int wid = threadIdx.x >> 5, lane = threadIdx.x & 31;
    const int row = blockIdx.x * 8 + wid;

    float4 a = g_part[lane][row];
    float4 b = g_part[lane + 32][row];
    float m = fmaxf(a.x, b.x);
    float l = a.y * ex2f(a.x - m) + b.y * ex2f(b.x - m);
    float ps = a.z + b.z;
#pragma unroll
    for (int off = 16; off > 0; off >>= 1) {
        float mo = __shfl_down_sync(0xFFFFFFFFu, m, off);
        float lo = __shfl_down_sync(0xFFFFFFFFu, l, off);
        float po = __shfl_down_sync(0xFFFFFFFFu, ps, off);
        float mn = fmaxf(m, mo);
        l = l * ex2f(m - mn) + lo * ex2f(mo - mn);
        m = mn; ps += po;
    }

    __shared__ float sred[8];
    const float LN2 = 0.6931471805599453f;
    const float T = 0.1f;
    if (lane == 0) {
        float cn = (float)(g_hist[(int)labels[row]] - 1);
        sred[wid] = (m + log2f(l)) * (LN2 * T / (float)NPTS) - ps / (cn * (float)NPTS);
    }
    __syncthreads();
    if (threadIdx.x < 8) {
        float v = sred[threadIdx.x];
#pragma unroll
        for (int off = 4; off > 0; off >>= 1)
            v += __shfl_down_sync(0xFFu, v, off);
        if (threadIdx.x == 0) atomicAdd(out, v);
    }
}

extern "C" void kernel_launch(void* const* d_in, const int* in_sizes, int n_in,
                              void* d_out, int out_size)
{
    const float*     emb    = (const float*)d_in[0];
    const long long* labels = (const long long*)d_in[1];
    float*           out    = (float*)d_out;

    cudaFuncSetAttribute(supcon_gemm, cudaFuncAttributeMaxDynamicSharedMemorySize, SM_TOTAL);

    supcon_zero<<<1, 32>>>(out);
    hist_kernel<<<NPTS / 256, 256>>>(labels);
    conv_kernel<<<NPTS * DDIM / 8 / 256, 256>>>(emb);
    supcon_gemm<<<NTILES_UT, 256, SM_TOTAL>>>(labels);
    supcon_reduce<<<NPTS / 8, 256>>>(labels, out);
}

// round 17
// speedup vs baseline: 1.0711x; 1.0165x over previous
#include <cuda_runtime.h>
#include <cuda_bf16.h>
#include <cstdint>
#include <math.h>

// SupCon loss, N=8192, D=512, T=0.1
// bf16 mma.sync GEMM, upper-triangular tiles (S symmetric), dual fused
// epilogue. 3-stage cp.async ring, prefetch-after-barrier, single barrier/stage.

#define NPTS 8192
#define DDIM 512
#define NBLK 64
#define NTILES_UT (NBLK * (NBLK + 1) / 2)   // 2080
#define NOFFD (NBLK * (NBLK - 1) / 2)       // 2016

// dynamic smem layout (bytes): 3-stage ring
#define SM_A    0            // 3 stages x 16384
#define SM_B    49152        // 3 stages x 16384
#define SM_RLAB 98304        // 128 int
#define SM_CLAB 98816        // 128 int
#define SM_REDR 99328        // 512 float4 = 8192
#define SM_REDC 107520       // 256 float4 = 4096
#define SM_TOTAL 111616

__device__ __nv_bfloat16 g_ebf[NPTS * DDIM];     // 8 MB bf16 embeddings
__device__ float4 g_part[NBLK][NPTS];            // 8 MB partials
__device__ int g_hist[16];

__device__ __forceinline__ uint32_t smem_u32(const void* p) {
    uint32_t a;
    asm("{ .reg .u64 t; cvta.to.shared.u64 t, %1; cvt.u32.u64 %0, t; }" : "=r"(a) : "l"(p));
    return a;
}
__device__ __forceinline__ float ex2f(float x) {
    float y; asm("ex2.approx.f32 %0, %1;" : "=f"(y) : "f"(x)); return y;
}
__device__ __forceinline__ void cpasync16(uint32_t saddr, const void* g) {
    asm volatile("cp.async.cg.shared.global [%0], [%1], 16;" :: "r"(saddr), "l"(g));
}
__device__ __forceinline__ void ldsm4(uint32_t* r, uint32_t addr) {
    asm volatile("ldmatrix.sync.aligned.m8n8.x4.shared.b16 {%0,%1,%2,%3}, [%4];"
                 : "=r"(r[0]), "=r"(r[1]), "=r"(r[2]), "=r"(r[3]) : "r"(addr));
}
__device__ __forceinline__ void mma_bf16(float* c, const uint32_t* a, uint32_t b0, uint32_t b1) {
    asm volatile("mma.sync.aligned.m16n8k16.row.col.f32.bf16.bf16.f32 "
                 "{%0,%1,%2,%3}, {%4,%5,%6,%7}, {%8,%9}, {%0,%1,%2,%3};"
                 : "+f"(c[0]), "+f"(c[1]), "+f"(c[2]), "+f"(c[3])
                 : "r"(a[0]), "r"(a[1]), "r"(a[2]), "r"(a[3]), "r"(b0), "r"(b1));
}

// ---------------- fp32 -> bf16 ----------------
__global__ void __launch_bounds__(256)
conv_kernel(const float* __restrict__ emb)
{
    int i = (blockIdx.x * 256 + threadIdx.x) * 8;
    float4 v0 = *reinterpret_cast<const float4*>(emb + i);
    float4 v1 = *reinterpret_cast<const float4*>(emb + i + 4);
    __nv_bfloat162 b0 = __float22bfloat162_rn(make_float2(v0.x, v0.y));
    __nv_bfloat162 b1 = __float22bfloat162_rn(make_float2(v0.z, v0.w));
    __nv_bfloat162 b2 = __float22bfloat162_rn(make_float2(v1.x, v1.y));
    __nv_bfloat162 b3 = __float22bfloat162_rn(make_float2(v1.z, v1.w));
    uint4 o;
    o.x = *reinterpret_cast<uint32_t*>(&b0);
    o.y = *reinterpret_cast<uint32_t*>(&b1);
    o.z = *reinterpret_cast<uint32_t*>(&b2);
    o.w = *reinterpret_cast<uint32_t*>(&b3);
    *reinterpret_cast<uint4*>(g_ebf + i) = o;
}

__global__ void supcon_zero(float* out) {
    if (threadIdx.x == 0) *out = 0.0f;
    if (threadIdx.x < 16) g_hist[threadIdx.x] = 0;
}

__global__ void __launch_bounds__(256)
hist_kernel(const long long* __restrict__ labels)
{
    __shared__ int h[16];
    if (threadIdx.x < 16) h[threadIdx.x] = 0;
    __syncthreads();
    atomicAdd(&h[(int)labels[blockIdx.x * 256 + threadIdx.x]], 1);
    __syncthreads();
    if (threadIdx.x < 16) atomicAdd(&g_hist[threadIdx.x], h[threadIdx.x]);
}

// ---------------- GEMM (upper-tri tiles) + dual fused epilogue ----------------
__global__ void __launch_bounds__(256, 2)
supcon_gemm(const long long* __restrict__ labels)
{
    extern __shared__ __align__(128) char smem[];
    int* rlab_s = (int*)(smem + SM_RLAB);
    int* clab_s = (int*)(smem + SM_CLAB);
    float4* red_r = (float4*)(smem + SM_REDR);
    float4* red_c = (float4*)(smem + SM_REDC);

    const int tid = threadIdx.x;
    const int wid = tid >> 5, lane = tid & 31;
    const int warp_m = wid >> 2, warp_n = wid & 3;

    // bid -> (I,J): off-diagonal tiles first, diagonal tiles last (cheap tail)
    int I, J;
    if (blockIdx.x < NOFFD) {
        int q = blockIdx.x; I = 0;
        while (q >= NBLK - 1 - I) { q -= NBLK - 1 - I; ++I; }
        J = I + 1 + q;
    } else {
        I = J = blockIdx.x - NOFFD;
    }
    const int row0 = I * 128, col0 = J * 128;
    const bool offdiag = (I != J);

    if (tid < 128) rlab_s[tid] = (int)labels[row0 + tid];
    else           clab_s[tid - 128] = (int)labels[col0 + tid - 128];

    const uint32_t aBase = smem_u32(smem + SM_A);
    const uint32_t bBase = smem_u32(smem + SM_B);

    // ---- cp.async mapping: row = tid>>1, half = tid&1 ----
    const int ldr = tid >> 1;
    const int ldh = tid & 1;
    const int swl = ldr & 7;
    uint32_t stA[4], stB[4];
#pragma unroll
    for (int j = 0; j < 4; ++j) {
        const uint32_t off = (uint32_t)(ldr * 128 + (((ldh * 4 + j) ^ swl) * 16));
        stA[j] = aBase + off;
        stB[j] = bBase + off;
    }
    const __nv_bfloat16* gA = g_ebf + (size_t)(row0 + ldr) * DDIM + ldh * 32;
    const __nv_bfloat16* gB = g_ebf + (size_t)(col0 + ldr) * DDIM + ldh * 32;

    // ---- ldmatrix addressing ----
    const int lrowA = warp_m * 64 + ((lane >> 3) & 1) * 8 + (lane & 7);
    const int lrowB = warp_n * 32 + ((lane >> 3) & 1) * 8 + (lane & 7);
    const int hi    = lane >> 4;
    const uint32_t rowA = aBase + (uint32_t)(lrowA * 128);
    const uint32_t rowB = bBase + (uint32_t)(lrowB * 128);
    uint32_t colA[4], colB[4];
#pragma unroll
    for (int s = 0; s < 4; ++s) {
        colA[s] = (uint32_t)((((2 * s + hi) ^ (lrowA & 7))) * 16);
        colB[s] = (uint32_t)((((2 * s + hi) ^ (lrowB & 7))) * 16);
    }

    float ca[4][4][4];
#pragma unroll
    for (int a = 0; a < 4; a++)
#pragma unroll
        for (int b = 0; b < 4; b++)
#pragma unroll
            for (int c = 0; c < 4; c++) ca[a][b][c] = 0.0f;

    // prologue: stages 0 and 1
#pragma unroll
    for (int p = 0; p < 2; ++p) {
        const uint32_t off = (uint32_t)(p * 16384);
        const __nv_bfloat16* ga = gA + p * 64;
        const __nv_bfloat16* gb = gB + p * 64;
#pragma unroll
        for (int j = 0; j < 4; ++j) {
            cpasync16(stA[j] + off, ga + j * 8);
            cpasync16(stB[j] + off, gb + j * 8);
        }
        asm volatile("cp.async.commit_group;");
    }

#pragma unroll
    for (int kt = 0; kt < 8; ++kt) {
        // pending groups at top: {kt, kt+1} (or just {kt..} at tail).
        // wait_group 1 -> stage kt landed; last iter must drain fully.
        if (kt < 7) asm volatile("cp.async.wait_group 1;");
        else        asm volatile("cp.async.wait_group 0;");
        __syncthreads();
        // All warps are past compute(kt-1): buffer (kt+2)%3 is free to refill.
        if (kt + 2 < 8) {
            const uint32_t off = (uint32_t)(((kt + 2) % 3) * 16384);
            const __nv_bfloat16* ga = gA + (kt + 2) * 64;
            const __nv_bfloat16* gb = gB + (kt + 2) * 64;
#pragma unroll
            for (int j = 0; j < 4; ++j) {
                cpasync16(stA[j] + off, ga + j * 8);
                cpasync16(stB[j] + off, gb + j * 8);
            }
            asm volatile("cp.async.commit_group;");
        }

        const uint32_t boff = (uint32_t)((kt % 3) * 16384);
#pragma unroll
        for (int s = 0; s < 4; ++s) {
            uint32_t af[4][4], bfr[2][4];
#pragma unroll
            for (int mf = 0; mf < 4; ++mf)
                ldsm4(af[mf], rowA + boff + colA[s] + (uint32_t)(mf * 2048));
#pragma unroll
            for (int ng = 0; ng < 2; ++ng)
                ldsm4(bfr[ng], rowB + boff + colB[s] + (uint32_t)(ng * 2048));
#pragma unroll
            for (int mf = 0; mf < 4; ++mf)
#pragma unroll
                for (int nf = 0; nf < 4; ++nf) {
                    int ng = nf >> 1, u = nf & 1;
                    mma_bf16(ca[mf][nf], af[mf], bfr[ng][u], bfr[ng][2 + u]);
                }
        }
    }

    const float Cc = 14.4269504088896341f;   // 1/(T*ln2), T=0.1
    const int g  = lane >> 2;
    const int qq = lane & 3;

    // hoist labels into registers: 8 rows, 8 cols per thread
    int rl[8], cl[8];
#pragma unroll
    for (int mf = 0; mf < 4; ++mf)
#pragma unroll
        for (int h = 0; h < 2; ++h)
            rl[mf * 2 + h] = rlab_s[warp_m * 64 + mf * 16 + h * 8 + g];
#pragma unroll
    for (int nf = 0; nf < 4; ++nf)
#pragma unroll
        for (int e = 0; e < 2; ++e)
            cl[nf * 2 + e] = clab_s[warp_n * 32 + nf * 8 + qq * 2 + e];

    if (offdiag) {
        // ---- row-side: per-row max, no diag checks ----
#pragma unroll
        for (int mf = 0; mf < 4; ++mf) {
#pragma unroll
            for (int h = 0; h < 2; ++h) {
                const int lrow = warp_m * 64 + mf * 16 + h * 8 + g;
                const int rlv = rl[mf * 2 + h];
                float tm = -1e30f, ps = 0.0f;
#pragma unroll
                for (int nf = 0; nf < 4; ++nf)
#pragma unroll
                    for (int e = 0; e < 2; ++e) {
                        const float d = ca[mf][nf][h * 2 + e];
                        tm = fmaxf(tm, d);
                        if (cl[nf * 2 + e] == rlv) ps += d;
                    }
                tm = fmaxf(tm, __shfl_xor_sync(0xFFFFFFFFu, tm, 1));
                tm = fmaxf(tm, __shfl_xor_sync(0xFFFFFFFFu, tm, 2));
                const float tms = tm * Cc;
                float l = 0.0f;
#pragma unroll
                for (int nf = 0; nf < 4; ++nf)
#pragma unroll
                    for (int e = 0; e < 2; ++e)
                        l += ex2f(fmaf(ca[mf][nf][h * 2 + e], Cc, -tms));
                l  += __shfl_xor_sync(0xFFFFFFFFu, l, 1);
                l  += __shfl_xor_sync(0xFFFFFFFFu, l, 2);
                ps += __shfl_xor_sync(0xFFFFFFFFu, ps, 1);
                ps += __shfl_xor_sync(0xFFFFFFFFu, ps, 2);
                if (qq == 0) red_r[lrow * 4 + warp_n] = make_float4(tms, l, ps, 0.0f);
            }
        }
        // ---- col-side: per-col max, no diag checks ----
#pragma unroll
        for (int nf = 0; nf < 4; ++nf) {
#pragma unroll
            for (int e = 0; e < 2; ++e) {
                const int lcol = warp_n * 32 + nf * 8 + qq * 2 + e;
                const int clv = cl[nf * 2 + e];
                float tm = -1e30f, ps = 0.0f;
#pragma unroll
                for (int mf = 0; mf < 4; ++mf)
#pragma unroll
                    for (int h = 0; h < 2; ++h) {
                        const float d = ca[mf][nf][h * 2 + e];
                        tm = fmaxf(tm, d);
                        if (rl[mf * 2 + h] == clv) ps += d;
                    }
                tm = fmaxf(tm, __shfl_xor_sync(0xFFFFFFFFu, tm, 4));
                tm = fmaxf(tm, __shfl_xor_sync(0xFFFFFFFFu, tm, 8));
                tm = fmaxf(tm, __shfl_xor_sync(0xFFFFFFFFu, tm, 16));
                const float tms = tm * Cc;
                float l = 0.0f;
#pragma unroll
                for (int mf = 0; mf < 4; ++mf)
#pragma unroll
                    for (int h = 0; h < 2; ++h)
                        l += ex2f(fmaf(ca[mf][nf][h * 2 + e], Cc, -tms));
                l  += __shfl_xor_sync(0xFFFFFFFFu, l, 4);
                l  += __shfl_xor_sync(0xFFFFFFFFu, l, 8);
                l  += __shfl_xor_sync(0xFFFFFFFFu, l, 16);
                ps += __shfl_xor_sync(0xFFFFFFFFu, ps, 4);
                ps += __shfl_xor_sync(0xFFFFFFFFu, ps, 8);
                ps += __shfl_xor_sync(0xFFFFFFFFu, ps, 16);
                if (g == 0) red_c[lcol * 2 + warp_m] = make_float4(tms, l, ps, 0.0f);
            }
        }
    } else {
        // ---- diagonal tile: exact path with per-element diag exclusion ----
#pragma unroll
        for (int mf = 0; mf < 4; ++mf) {
#pragma unroll
            for (int h = 0; h < 2; ++h) {
                const int lrow = warp_m * 64 + mf * 16 + h * 8 + g;
                const int grow = row0 + lrow;
                const int rlv = rl[mf * 2 + h];
                float tm = -1e30f, ps = 0.0f;
#pragma unroll
                for (int nf = 0; nf < 4; ++nf)
#pragma unroll
                    for (int e = 0; e < 2; ++e) {
                        const int lcol = warp_n * 32 + nf * 8 + qq * 2 + e;
                        const float d = ca[mf][nf][h * 2 + e];
                        const bool diag = (grow == col0 + lcol);
                        if (!diag) tm = fmaxf(tm, d);
                        if (!diag && cl[nf * 2 + e] == rlv) ps += d;
                    }
                tm = fmaxf(tm, __shfl_xor_sync(0xFFFFFFFFu, tm, 1));
                tm = fmaxf(tm, __shfl_xor_sync(0xFFFFFFFFu, tm, 2));
                const float tms = tm * Cc;
                float l = 0.0f;
#pragma unroll
                for (int nf = 0; nf < 4; ++nf)
#pragma unroll
                    for (int e = 0; e < 2; ++e) {
                        const int lcol = warp_n * 32 + nf * 8 + qq * 2 + e;
                        const bool diag = (grow == col0 + lcol);
                        if (!diag) l += ex2f(fmaf(ca[mf][nf][h * 2 + e], Cc, -tms));
                    }
                l  += __shfl_xor_sync(0xFFFFFFFFu, l, 1);
                l  += __shfl_xor_sync(0xFFFFFFFFu, l, 2);
                ps += __shfl_xor_sync(0xFFFFFFFFu, ps, 1);
                ps += __shfl_xor_sync(0xFFFFFFFFu, ps, 2);
                if (qq == 0) red_r[lrow * 4 + warp_n] = make_float4(tms, l, ps, 0.0f);
            }
        }
    }

    __syncthreads();

    // ---- intra-CTA merges + partial writes ----
    if (tid < 128) {
        float4 p0 = red_r[tid * 4 + 0];
        float4 p1 = red_r[tid * 4 + 1];
        float4 p2 = red_r[tid * 4 + 2];
        float4 p3 = red_r[tid * 4 + 3];
        float m = fmaxf(fmaxf(p0.x, p1.x), fmaxf(p2.x, p3.x));
        float l = p0.y * ex2f(p0.x - m) + p1.y * ex2f(p1.x - m)
                + p2.y * ex2f(p2.x - m) + p3.y * ex2f(p3.x - m);
        g_part[J][row0 + tid] = make_float4(m, l, p0.z + p1.z + p2.z + p3.z, 0.0f);
    } else if (offdiag) {
        const int c = tid - 128;
        float4 p = red_c[c * 2 + 0];
        float4 q = red_c[c * 2 + 1];
        float mn = fmaxf(p.x, q.x);
        float l = p.y * ex2f(p.x - mn) + q.y * ex2f(q.x - mn);
        g_part[I][col0 + c] = make_float4(mn, l, p.z + q.z, 0.0f);
    }
}

// ---------------- final per-row merge + loss reduction ----------------
__global__ void __launch_bounds__(256)
supcon_reduce(const long long* __restrict__ labels, float* __restrict__ out)
{
    const int wid = threadIdx.x >> 5, lane = threadIdx.x & 31;
    const int row = blockIdx.x * 8 + wid;

    float4 a = g_part[lane][row];
    float4 b = g_part[lane + 32][row];
    float m = fmaxf(a.x, b.x);
    float l = a.y * ex2f(a.x - m) + b.y * ex2f(b.x - m);
    float ps = a.z + b.z;
#pragma unroll
    for (int off = 16; off > 0; off >>= 1) {
        float mo = __shfl_down_sync(0xFFFFFFFFu, m, off);
        float lo = __shfl_down_sync(0xFFFFFFFFu, l, off);
        float po = __shfl_down_sync(0xFFFFFFFFu, ps, off);
        float mn = fmaxf(m, mo);
        l = l * ex2f(m - mn) + lo * ex2f(mo - mn);
        m = mn; ps += po;
    }

    __shared__ float sred[8];
    const float LN2 = 0.6931471805599453f;
    const float T = 0.1f;
    if (lane == 0) {
        float cn = (float)(g_hist[(int)labels[row]] - 1);
        sred[wid] = (m + log2f(l)) * (LN2 * T / (float)NPTS) - ps / (cn * (float)NPTS);
    }
    __syncthreads();
    if (threadIdx.x < 8) {
        float v = sred[threadIdx.x];
#pragma unroll
        for (int off = 4; off > 0; off >>= 1)
            v += __shfl_down_sync(0xFFu, v, off);
        if (threadIdx.x == 0) atomicAdd(out, v);
    }
}

extern "C" void kernel_launch(void* const* d_in, const int* in_sizes, int n_in,
                              void* d_out, int out_size)
{
    const float*     emb    = (const float*)d_in[0];
    const long long* labels = (const long long*)d_in[1];
    float*           out    = (float*)d_out;

    cudaFuncSetAttribute(supcon_gemm, cudaFuncAttributeMaxDynamicSharedMemorySize, SM_TOTAL);

    supcon_zero<<<1, 32>>>(out);
    hist_kernel<<<NPTS / 256, 256>>>(labels);
    conv_kernel<<<NPTS * DDIM / 8 / 256, 256>>>(emb);
    supcon_gemm<<<NTILES_UT, 256, SM_TOTAL>>>(labels);
    supcon_reduce<<<NPTS / 8, 256>>>(labels, out);
}